// round 11
// baseline (speedup 1.0000x reference)
#include <cuda_runtime.h>
#include <math.h>

#define BATCH   4
#define NTOK    512
#define DMODEL  512
#define NH      8
#define DKH     64

// ---------------- device scratch (no allocations allowed) ----------------
__device__ float g_Q[BATCH*NH*NTOK*DKH];     // 4 MB
__device__ float g_K[BATCH*NH*NTOK*DKH];     // 4 MB
__device__ float g_V[BATCH*NH*NTOK*DKH];     // 4 MB
__device__ float g_BIAS[BATCH*NH*NTOK*NTOK]; // 32 MB
__device__ float g_CTX[BATCH*NTOK*DMODEL];   // 4 MB

// ---------------- helpers ----------------
__device__ __forceinline__ unsigned f2tf32(float x) {
    unsigned b;
    asm("cvt.rna.tf32.f32 %0, %1;" : "=r"(b) : "f"(x));
    return b;
}
__device__ __forceinline__ float f2tf32f(float x) {
    return __uint_as_float(f2tf32(x));
}

__device__ __forceinline__ void mma_tf32(float& c0, float& c1, float& c2, float& c3,
                                         unsigned a0, unsigned a1, unsigned a2, unsigned a3,
                                         unsigned b0, unsigned b1) {
    asm volatile("mma.sync.aligned.m16n8k8.row.col.f32.tf32.tf32.f32 "
                 "{%0,%1,%2,%3}, {%4,%5,%6,%7}, {%8,%9}, {%0,%1,%2,%3};"
                 : "+f"(c0), "+f"(c1), "+f"(c2), "+f"(c3)
                 : "r"(a0), "r"(a1), "r"(a2), "r"(a3), "r"(b0), "r"(b1));
}

// =====================================================================
// Kernel 1: geometry bias.  grid (NTOK, BATCH), 256 threads.
// ONLY change this round: sincosf/logf -> MUFU __sincosf/__logf.
// =====================================================================
__global__ void geom_kernel(const float* __restrict__ box,
                            const float* __restrict__ WG,
                            const float* __restrict__ bG)
{
    __shared__ float sWGs[32][8];
    __shared__ float sWGc[32][8];
    __shared__ float sbG[8];

    const int b = blockIdx.y;
    const int i = blockIdx.x;
    const int tid = threadIdx.x;

    for (int e = tid; e < 512; e += blockDim.x) {
        int h = e >> 6, g = e & 63;
        float v = WG[e];
        if (g < 32) sWGs[g][h] = v;
        else        sWGc[g - 32][h] = v;
    }
    if (tid < 8) sbG[tid] = bG[tid];

    const float4 bi = *(const float4*)(box + ((long)b*NTOK + i)*4);
    const float cxi = 0.5f*(bi.x + bi.z);
    const float cyi = 0.5f*(bi.y + bi.w);
    const float wi  = bi.z - bi.x + 1.0f;
    const float hi  = bi.w - bi.y + 1.0f;
    const float lwi = __logf(wi);
    const float lhi = __logf(hi);
    __syncthreads();

    const float dm[8] = {1.0f, 0.4216965034f, 0.1778279410f, 0.0749894209f,
                         0.0316227766f, 0.0133352143f, 0.0056234133f, 0.0023713737f};

    float* outb = g_BIAS + ((long)b*NH*NTOK + i)*NTOK;

    for (int j = tid; j < NTOK; j += blockDim.x) {
        float4 bj = *(const float4*)(box + ((long)b*NTOK + j)*4);
        float cxj = 0.5f*(bj.x + bj.z);
        float cyj = 0.5f*(bj.y + bj.w);
        float wj  = bj.z - bj.x + 1.0f;
        float hj  = bj.w - bj.y + 1.0f;

        float a0 = 100.0f * __logf(fmaxf(fabsf(cxi - cxj) / wi, 1e-3f));
        float a1 = 100.0f * __logf(fmaxf(fabsf(cyi - cyj) / hi, 1e-3f));
        float a2 = 100.0f * (lwi - __logf(wj));
        float a3 = 100.0f * (lhi - __logf(hj));
        float a[4] = {a0, a1, a2, a3};

        float acc[8];
        #pragma unroll
        for (int h = 0; h < 8; h++) acc[h] = sbG[h];

        #pragma unroll
        for (int f = 0; f < 4; f++) {
            #pragma unroll
            for (int r = 0; r < 8; r++) {
                float s, c;
                __sincosf(a[f] * dm[r], &s, &c);
                const int t = f*8 + r;
                #pragma unroll
                for (int h = 0; h < 8; h++)
                    acc[h] += s * sWGs[t][h] + c * sWGc[t][h];
            }
        }
        #pragma unroll
        for (int h = 0; h < 8; h++) {
            float wg = fmaxf(acc[h], 1e-6f);
            outb[(long)h*NTOK*NTOK + j] = __logf(wg);
        }
    }
}

// =====================================================================
// TF32 GEMM core: 64x64 tile, 128 threads, single-buffer smem +
// register prefetch, stride-72 conflict-free. K range [kbeg, kend).
// =====================================================================
template<typename WriteFn>
__device__ __forceinline__ void gemm64_core(
    const float* __restrict__ X, const float* __restrict__ W,
    int m0, int n0, int kbeg, int kend, WriteFn&& write)
{
    __shared__ float As[16][72];
    __shared__ float Bs[16][72];

    const int tid = threadIdx.x;
    const int lm = tid >> 1;
    const int lk = (tid & 1) * 8;

    const float* Aptr = X + (long)(m0 + lm)*512 + lk;
    const float* Bptr = W + (long)(n0 + lm)*512 + lk;

    float4 xa = *(const float4*)(Aptr + kbeg);
    float4 xb = *(const float4*)(Aptr + kbeg + 4);
    float4 wa = *(const float4*)(Bptr + kbeg);
    float4 wb = *(const float4*)(Bptr + kbeg + 4);

    const int w    = tid >> 5;
    const int wm   = (w & 1) * 32;
    const int wn2  = (w >> 1) * 32;
    const int lane = tid & 31;
    const int lr   = lane >> 2;
    const int lc   = lane & 3;

    float acc[2][4][4];
    #pragma unroll
    for (int mi = 0; mi < 2; mi++)
        #pragma unroll
        for (int ni = 0; ni < 4; ni++)
            #pragma unroll
            for (int q = 0; q < 4; q++) acc[mi][ni][q] = 0.0f;

    for (int k0 = kbeg; k0 < kend; k0 += 16) {
        As[lk+0][lm]=f2tf32f(xa.x); As[lk+1][lm]=f2tf32f(xa.y);
        As[lk+2][lm]=f2tf32f(xa.z); As[lk+3][lm]=f2tf32f(xa.w);
        As[lk+4][lm]=f2tf32f(xb.x); As[lk+5][lm]=f2tf32f(xb.y);
        As[lk+6][lm]=f2tf32f(xb.z); As[lk+7][lm]=f2tf32f(xb.w);
        Bs[lk+0][lm]=f2tf32f(wa.x); Bs[lk+1][lm]=f2tf32f(wa.y);
        Bs[lk+2][lm]=f2tf32f(wa.z); Bs[lk+3][lm]=f2tf32f(wa.w);
        Bs[lk+4][lm]=f2tf32f(wb.x); Bs[lk+5][lm]=f2tf32f(wb.y);
        Bs[lk+6][lm]=f2tf32f(wb.z); Bs[lk+7][lm]=f2tf32f(wb.w);
        __syncthreads();

        if (k0 + 16 < kend) {
            xa = *(const float4*)(Aptr + k0 + 16);
            xb = *(const float4*)(Aptr + k0 + 20);
            wa = *(const float4*)(Bptr + k0 + 16);
            wb = *(const float4*)(Bptr + k0 + 20);
        }

        #pragma unroll
        for (int ks = 0; ks < 2; ks++) {
            const int kb = ks * 8;
            unsigned afr[2][4];
            #pragma unroll
            for (int mi = 0; mi < 2; mi++) {
                const int mrow = wm + 16*mi;
                afr[mi][0] = __float_as_uint(As[kb + lc    ][mrow + lr    ]);
                afr[mi][1] = __float_as_uint(As[kb + lc    ][mrow + lr + 8]);
                afr[mi][2] = __float_as_uint(As[kb + lc + 4][mrow + lr    ]);
                afr[mi][3] = __float_as_uint(As[kb + lc + 4][mrow + lr + 8]);
            }
            unsigned bfr[4][2];
            #pragma unroll
            for (int ni = 0; ni < 4; ni++) {
                const int ncol = wn2 + 8*ni;
                bfr[ni][0] = __float_as_uint(Bs[kb + lc    ][ncol + lr]);
                bfr[ni][1] = __float_as_uint(Bs[kb + lc + 4][ncol + lr]);
            }
            #pragma unroll
            for (int mi = 0; mi < 2; mi++)
                #pragma unroll
                for (int ni = 0; ni < 4; ni++)
                    mma_tf32(acc[mi][ni][0], acc[mi][ni][1],
                             acc[mi][ni][2], acc[mi][ni][3],
                             afr[mi][0], afr[mi][1], afr[mi][2], afr[mi][3],
                             bfr[ni][0], bfr[ni][1]);
        }
        __syncthreads();
    }

    #pragma unroll
    for (int mi = 0; mi < 2; mi++) {
        #pragma unroll
        for (int ni = 0; ni < 4; ni++) {
            const int row = wm + 16*mi + lr;
            const int col = wn2 + 8*ni + 2*lc;
            write(row,     col, acc[mi][ni][0], acc[mi][ni][1]);
            write(row + 8, col, acc[mi][ni][2], acc[mi][ni][3]);
        }
    }
}

// ---- fused QKV projection (head-split write) ----
__global__ void __launch_bounds__(128) qkv_kernel(
    const float* __restrict__ Xq, const float* __restrict__ Xk, const float* __restrict__ Xv,
    const float* __restrict__ Wq, const float* __restrict__ Wk, const float* __restrict__ Wv,
    const float* __restrict__ bq, const float* __restrict__ bk, const float* __restrict__ bv)
{
    const int z = blockIdx.z;
    const float* X    = (z == 0) ? Xq : (z == 1) ? Xk : Xv;
    const float* W    = (z == 0) ? Wq : (z == 1) ? Wk : Wv;
    const float* bias = (z == 0) ? bq : (z == 1) ? bk : bv;
    float*       Y    = (z == 0) ? g_Q : (z == 1) ? g_K : g_V;

    const int m0 = blockIdx.y * 64;
    const int n0 = blockIdx.x * 64;
    const int h  = n0 >> 6;

    gemm64_core(X, W, m0, n0, 0, 512,
        [&](int row, int col, float v0, float v1) {
            int m = m0 + row;
            int b = m >> 9, n = m & 511;
            float2 r;
            r.x = v0 + bias[n0 + col];
            r.y = v1 + bias[n0 + col + 1];
            *(float2*)(Y + (((long)(b*NH + h)*NTOK + n)*DKH) + col) = r;
        });
}

// ---- zero-init for split-K accumulation target ----
__global__ void zero_kernel(float4* __restrict__ p, int n4)
{
    int i = blockIdx.x * blockDim.x + threadIdx.x;
    if (i < n4) p[i] = make_float4(0.f, 0.f, 0.f, 0.f);
}

// ---- output projection, split-K=2 (atomicAdd; 2 adds/elem = commutative,
//      hence bit-deterministic) ----
__global__ void __launch_bounds__(128) oproj_kernel(
    const float* __restrict__ W, const float* __restrict__ bias,
    float* __restrict__ Yout)
{
    const int m0 = blockIdx.y * 64;
    const int n0 = blockIdx.x * 64;
    const int z  = blockIdx.z;           // k-half
    const int kbeg = z * 256, kend = kbeg + 256;

    gemm64_core(g_CTX, W, m0, n0, kbeg, kend,
        [&](int row, int col, float v0, float v1) {
            float b0 = (z == 0) ? bias[n0 + col]     : 0.0f;
            float b1 = (z == 0) ? bias[n0 + col + 1] : 0.0f;
            float* p = Yout + (long)(m0 + row)*512 + n0 + col;
            atomicAdd(p,     v0 + b0);
            atomicAdd(p + 1, v1 + b1);
        });
}

// =====================================================================
// Kernel 3: flash attention, TF32 mma, latency-hidden staging.
// (unchanged)
// =====================================================================
#define QS_STRIDE 68
#define KS_STRIDE 72

__global__ void __launch_bounds__(128) attn_kernel()
{
    extern __shared__ float sm[];
    float* Qs = sm;                      // [64][68]  m-major (tf32, x0.125)
    float* Ks = Qs + 64*QS_STRIDE;       // [64][72]  k-major
    float* Vs = Ks + 64*KS_STRIDE;       // [64][72]  token-major
    float* Ps = Vs + 64*KS_STRIDE;       // [64][68]  m-major

    const int tid  = threadIdx.x;
    const int lane = tid & 31;
    const int w    = tid >> 5;
    const int wm   = w * 16;
    const int lr   = lane >> 2;
    const int lc   = lane & 3;

    const int bh = blockIdx.x;
    const int q0 = blockIdx.y * 64;

    const float* Qg = g_Q   + (long)bh*NTOK*DKH + (long)q0*DKH;
    const float* Kg = g_K   + (long)bh*NTOK*DKH;
    const float* Vg = g_V   + (long)bh*NTOK*DKH;
    const float* Bg = g_BIAS + (long)bh*NTOK*NTOK + (long)q0*NTOK;

    const int n  = tid >> 1;
    const int kq = (tid & 1) * 32;

    {
        const float* src = Qg + n*64 + kq;
        #pragma unroll
        for (int u = 0; u < 8; u++) {
            float4 v = *(const float4*)(src + u*4);
            Qs[n*QS_STRIDE + kq + u*4 + 0] = f2tf32f(v.x * 0.125f);
            Qs[n*QS_STRIDE + kq + u*4 + 1] = f2tf32f(v.y * 0.125f);
            Qs[n*QS_STRIDE + kq + u*4 + 2] = f2tf32f(v.z * 0.125f);
            Qs[n*QS_STRIDE + kq + u*4 + 3] = f2tf32f(v.w * 0.125f);
        }
    }

    float4 kreg[8];
    {
        const float* srcK = Kg + (long)n*64 + kq;
        #pragma unroll
        for (int u = 0; u < 8; u++) kreg[u] = *(const float4*)(srcK + u*4);
    }

    float m_i[2] = {-1e30f, -1e30f};
    float l_i[2] = {0.0f, 0.0f};
    float o[8][4];
    #pragma unroll
    for (int d = 0; d < 8; d++)
        #pragma unroll
        for (int q = 0; q < 4; q++) o[d][q] = 0.0f;

    for (int t = 0; t < 8; t++) {
        __syncthreads();

        #pragma unroll
        for (int u = 0; u < 8; u++) {
            Ks[(kq+u*4+0)*KS_STRIDE + n] = f2tf32f(kreg[u].x);
            Ks[(kq+u*4+1)*KS_STRIDE + n] = f2tf32f(kreg[u].y);
            Ks[(kq+u*4+2)*KS_STRIDE + n] = f2tf32f(kreg[u].z);
            Ks[(kq+u*4+3)*KS_STRIDE + n] = f2tf32f(kreg[u].w);
        }

        if (t < 7) {
            const float* srcK = Kg + (long)((t+1)*64 + n)*64 + kq;
            #pragma unroll
            for (int u = 0; u < 8; u++) kreg[u] = *(const float4*)(srcK + u*4);
        }

        float4 vreg[8];
        {
            const float* srcV = Vg + (long)(t*64 + n)*64 + kq;
            #pragma unroll
            for (int u = 0; u < 8; u++) vreg[u] = *(const float4*)(srcV + u*4);
        }

        float2 breg0[8], breg1[8];
        {
            const float* brow0 = Bg + (long)(wm+lr  )*512 + t*64;
            const float* brow1 = Bg + (long)(wm+lr+8)*512 + t*64;
            #pragma unroll
            for (int nc = 0; nc < 8; nc++) {
                breg0[nc] = *(const float2*)(brow0 + 8*nc + 2*lc);
                breg1[nc] = *(const float2*)(brow1 + 8*nc + 2*lc);
            }
        }
        __syncthreads();

        float sacc[8][4];
        #pragma unroll
        for (int nc = 0; nc < 8; nc++)
            #pragma unroll
            for (int q = 0; q < 4; q++) sacc[nc][q] = 0.0f;

        #pragma unroll
        for (int ks = 0; ks < 8; ks++) {
            const int kb = ks * 8;
            unsigned a0 = __float_as_uint(Qs[(wm+lr  )*QS_STRIDE + kb + lc    ]);
            unsigned a1 = __float_as_uint(Qs[(wm+lr+8)*QS_STRIDE + kb + lc    ]);
            unsigned a2 = __float_as_uint(Qs[(wm+lr  )*QS_STRIDE + kb + lc + 4]);
            unsigned a3 = __float_as_uint(Qs[(wm+lr+8)*QS_STRIDE + kb + lc + 4]);
            #pragma unroll
            for (int nc = 0; nc < 8; nc++) {
                unsigned b0 = __float_as_uint(Ks[(kb+lc  )*KS_STRIDE + 8*nc + lr]);
                unsigned b1 = __float_as_uint(Ks[(kb+lc+4)*KS_STRIDE + 8*nc + lr]);
                mma_tf32(sacc[nc][0], sacc[nc][1], sacc[nc][2], sacc[nc][3],
                         a0, a1, a2, a3, b0, b1);
            }
        }

        #pragma unroll
        for (int u = 0; u < 8; u++) {
            float4 cv;
            cv.x = f2tf32f(vreg[u].x); cv.y = f2tf32f(vreg[u].y);
            cv.z = f2tf32f(vreg[u].z); cv.w = f2tf32f(vreg[u].w);
            *(float4*)&Vs[n*KS_STRIDE + kq + u*4] = cv;
        }

        #pragma unroll
        for (int nc = 0; nc < 8; nc++) {
            sacc[nc][0] += breg0[nc].x; sacc[nc][1] += breg0[nc].y;
            sacc[nc][2] += breg1[nc].x; sacc[nc][3] += breg1[nc].y;
        }

        #pragma unroll
        for (int i = 0; i < 2; i++) {
            float tm = -1e30f;
            #pragma unroll
            for (int nc = 0; nc < 8; nc++)
                tm = fmaxf(tm, fmaxf(sacc[nc][2*i], sacc[nc][2*i+1]));
            tm = fmaxf(tm, __shfl_xor_sync(0xffffffffu, tm, 1));
            tm = fmaxf(tm, __shfl_xor_sync(0xffffffffu, tm, 2));
            float mnew = fmaxf(m_i[i], tm);
            float scale = __expf(m_i[i] - mnew);
            m_i[i] = mnew;

            float s = 0.0f;
            #pragma unroll
            for (int nc = 0; nc < 8; nc++) {
                float p0 = __expf(sacc[nc][2*i]   - mnew);
                float p1 = __expf(sacc[nc][2*i+1] - mnew);
                sacc[nc][2*i]   = p0;
                sacc[nc][2*i+1] = p1;
                s += p0 + p1;
            }
            s += __shfl_xor_sync(0xffffffffu, s, 1);
            s += __shfl_xor_sync(0xffffffffu, s, 2);
            l_i[i] = l_i[i]*scale + s;

            #pragma unroll
            for (int d = 0; d < 8; d++) {
                o[d][2*i]   *= scale;
                o[d][2*i+1] *= scale;
            }
        }

        #pragma unroll
        for (int nc = 0; nc < 8; nc++) {
            float2 p0, p1;
            p0.x = f2tf32f(sacc[nc][0]); p0.y = f2tf32f(sacc[nc][1]);
            p1.x = f2tf32f(sacc[nc][2]); p1.y = f2tf32f(sacc[nc][3]);
            *(float2*)&Ps[(wm+lr  )*QS_STRIDE + 8*nc + 2*lc] = p0;
            *(float2*)&Ps[(wm+lr+8)*QS_STRIDE + 8*nc + 2*lc] = p1;
        }
        __syncthreads();

        #pragma unroll
        for (int ks = 0; ks < 8; ks++) {
            const int kb = ks * 8;
            unsigned a0 = __float_as_uint(Ps[(wm+lr  )*QS_STRIDE + kb + lc    ]);
            unsigned a1 = __float_as_uint(Ps[(wm+lr+8)*QS_STRIDE + kb + lc    ]);
            unsigned a2 = __float_as_uint(Ps[(wm+lr  )*QS_STRIDE + kb + lc + 4]);
            unsigned a3 = __float_as_uint(Ps[(wm+lr+8)*QS_STRIDE + kb + lc + 4]);
            #pragma unroll
            for (int dc = 0; dc < 8; dc++) {
                unsigned b0 = __float_as_uint(Vs[(kb+lc  )*KS_STRIDE + 8*dc + lr]);
                unsigned b1 = __float_as_uint(Vs[(kb+lc+4)*KS_STRIDE + 8*dc + lr]);
                mma_tf32(o[dc][0], o[dc][1], o[dc][2], o[dc][3],
                         a0, a1, a2, a3, b0, b1);
            }
        }
    }

    const int b = bh >> 3, h = bh & 7;
    const float inv0 = 1.0f / l_i[0];
    const float inv1 = 1.0f / l_i[1];
    float* ctx0 = g_CTX + ((long)(b*NTOK + q0 + wm + lr    ))*512 + h*64;
    float* ctx1 = g_CTX + ((long)(b*NTOK + q0 + wm + lr + 8))*512 + h*64;
    #pragma unroll
    for (int dc = 0; dc < 8; dc++) {
        float2 r0, r1;
        r0.x = o[dc][0]*inv0; r0.y = o[dc][1]*inv0;
        r1.x = o[dc][2]*inv1; r1.y = o[dc][3]*inv1;
        *(float2*)(ctx0 + 8*dc + 2*lc) = r0;
        *(float2*)(ctx1 + 8*dc + 2*lc) = r1;
    }
}

// =====================================================================
// launch
// =====================================================================
extern "C" void kernel_launch(void* const* d_in, const int* in_sizes, int n_in,
                              void* d_out, int out_size)
{
    const float* in_q  = (const float*)d_in[0];
    const float* in_k  = (const float*)d_in[1];
    const float* in_v  = (const float*)d_in[2];
    const float* box   = (const float*)d_in[3];
    const float* Wq    = (const float*)d_in[4];
    const float* bq    = (const float*)d_in[5];
    const float* Wk    = (const float*)d_in[6];
    const float* bk    = (const float*)d_in[7];
    const float* Wv    = (const float*)d_in[8];
    const float* bv    = (const float*)d_in[9];
    const float* Wo    = (const float*)d_in[10];
    const float* bo    = (const float*)d_in[11];
    const float* WG    = (const float*)d_in[12];
    const float* bG    = (const float*)d_in[13];
    float* out = (float*)d_out;

    const int ATTN_SMEM = (2*64*QS_STRIDE + 2*64*KS_STRIDE) * (int)sizeof(float); // 71680
    cudaFuncSetAttribute(attn_kernel, cudaFuncAttributeMaxDynamicSharedMemorySize, ATTN_SMEM);

    // geometry bias (MUFU fast-math — the one change this round)
    geom_kernel<<<dim3(NTOK, BATCH), 256>>>(box, WG, bG);

    // fused Q/K/V projections (tf32 tensor cores)
    qkv_kernel<<<dim3(512/64, 2048/64, 3), 128>>>(in_q, in_k, in_v,
                                                  Wq, Wk, Wv, bq, bk, bv);

    // attention (tf32 tensor cores, latency-hidden staging)
    attn_kernel<<<dim3(BATCH*NH, NTOK/64), 128, ATTN_SMEM>>>();

    // output projection -> d_out (split-K=2, zero-init + atomic accumulate)
    {
        const int n4 = (BATCH*NTOK*DMODEL) / 4;   // 262144 float4
        zero_kernel<<<(n4 + 255)/256, 256>>>((float4*)out, n4);
        oproj_kernel<<<dim3(512/64, 2048/64, 2), 128>>>(Wo, bo, out);
    }
}

// round 12
// speedup vs baseline: 1.3689x; 1.3689x over previous
#include <cuda_runtime.h>
#include <math.h>

#define BATCH   4
#define NTOK    512
#define DMODEL  512
#define NH      8
#define DKH     64

// ---------------- device scratch (no allocations allowed) ----------------
__device__ float g_Q[BATCH*NH*NTOK*DKH];     // 4 MB
__device__ float g_K[BATCH*NH*NTOK*DKH];     // 4 MB
__device__ float g_V[BATCH*NH*NTOK*DKH];     // 4 MB
__device__ float g_BIAS[BATCH*NH*NTOK*NTOK]; // 32 MB
__device__ float g_CTX[BATCH*NTOK*DMODEL];   // 4 MB
__device__ float g_TBL[BATCH*NTOK*32];       // 256 KB per-box sin/cos table

// ---------------- helpers ----------------
__device__ __forceinline__ unsigned f2tf32(float x) {
    unsigned b;
    asm("cvt.rna.tf32.f32 %0, %1;" : "=r"(b) : "f"(x));
    return b;
}
__device__ __forceinline__ float f2tf32f(float x) {
    return __uint_as_float(f2tf32(x));
}

__device__ __forceinline__ void mma_tf32(float& c0, float& c1, float& c2, float& c3,
                                         unsigned a0, unsigned a1, unsigned a2, unsigned a3,
                                         unsigned b0, unsigned b1) {
    asm volatile("mma.sync.aligned.m16n8k8.row.col.f32.tf32.tf32.f32 "
                 "{%0,%1,%2,%3}, {%4,%5,%6,%7}, {%8,%9}, {%0,%1,%2,%3};"
                 : "+f"(c0), "+f"(c1), "+f"(c2), "+f"(c3)
                 : "r"(a0), "r"(a1), "r"(a2), "r"(a3), "r"(b0), "r"(b1));
}

__constant__ float c_dm[8] = {1.0f, 0.4216965034f, 0.1778279410f, 0.0749894209f,
                              0.0316227766f, 0.0133352143f, 0.0056234133f, 0.0023713737f};

// =====================================================================
// Kernel 0: per-box sin/cos table for separable dw/dh features.
// layout per box: [sw 0..7 | cw 0..7 | sh 0..7 | ch 0..7],
// phi = 100*log(s)*dm[r].  SOFTWARE sincosf/logf (MUFU is banned).
// =====================================================================
__global__ void geom_table_kernel(const float* __restrict__ box)
{
    int idx = blockIdx.x * blockDim.x + threadIdx.x;
    if (idx >= BATCH*NTOK) return;
    float4 bx = *(const float4*)(box + (long)idx*4);
    float lw = 100.0f * logf(bx.z - bx.x + 1.0f);
    float lh = 100.0f * logf(bx.w - bx.y + 1.0f);
    float* t = g_TBL + (long)idx*32;
    for (int r = 0; r < 8; r++) {
        float s, c;
        sincosf(lw * c_dm[r], &s, &c);
        t[r] = s; t[8+r] = c;
        sincosf(lh * c_dm[r], &s, &c);
        t[16+r] = s; t[24+r] = c;
    }
}

// =====================================================================
// Kernel 1: geometry bias. grid (NTOK, BATCH), 256 threads.
// dx/dy: 16 software sincos per pair. dw/dh: exact angle-addition from
// the per-box table (0 sincos). All transcendentals = software libdevice.
// =====================================================================
__global__ void geom_kernel(const float* __restrict__ box,
                            const float* __restrict__ WG,
                            const float* __restrict__ bG)
{
    __shared__ float sWGs[16][8];   // sin weights, t=0..15 (dx,dy)
    __shared__ float sWGc[16][8];   // cos weights, t=0..15
    __shared__ float sP[16][8];     // separable: coeff of c_j
    __shared__ float sQ[16][8];     // separable: coeff of s_j
    __shared__ float sbG[8];

    const int b = blockIdx.y;
    const int i = blockIdx.x;
    const int tid = threadIdx.x;

    // dx/dy weights: sin at WG[h*64 + t], cos at WG[h*64 + 32 + t], t<16
    for (int e = tid; e < 128; e += blockDim.x) {
        int t = e >> 3, h = e & 7;
        sWGs[t][h] = WG[h*64 + t];
        sWGc[t][h] = WG[h*64 + 32 + t];
    }
    // separable coeffs folded with i-side table:
    // contribution = cj*(ci*Wc + si*Ws) + sj*(si*Wc - ci*Ws)
    {
        const float* ti = g_TBL + ((long)b*NTOK + i)*32;
        for (int e = tid; e < 128; e += blockDim.x) {
            int st = e >> 3, h = e & 7;            // st: 0..7 dw, 8..15 dh
            int feat = st >> 3, r = st & 7;
            float si = ti[feat*16 + r];
            float ci = ti[feat*16 + 8 + r];
            float Ws = WG[h*64 + 16 + st];
            float Wc = WG[h*64 + 48 + st];
            sP[st][h] = ci*Wc + si*Ws;
            sQ[st][h] = si*Wc - ci*Ws;
        }
    }
    if (tid < 8) sbG[tid] = bG[tid];

    const float4 bi = *(const float4*)(box + ((long)b*NTOK + i)*4);
    const float cxi = 0.5f*(bi.x + bi.z);
    const float cyi = 0.5f*(bi.y + bi.w);
    const float wi  = bi.z - bi.x + 1.0f;
    const float hi  = bi.w - bi.y + 1.0f;
    __syncthreads();

    const float dm[8] = {1.0f, 0.4216965034f, 0.1778279410f, 0.0749894209f,
                         0.0316227766f, 0.0133352143f, 0.0056234133f, 0.0023713737f};

    float* outb = g_BIAS + ((long)b*NH*NTOK + i)*NTOK;
    const float* tblb = g_TBL + (long)b*NTOK*32;

    for (int j = tid; j < NTOK; j += blockDim.x) {
        float4 bj = *(const float4*)(box + ((long)b*NTOK + j)*4);
        float cxj = 0.5f*(bj.x + bj.z);
        float cyj = 0.5f*(bj.y + bj.w);

        float a0 = 100.0f * logf(fmaxf(fabsf(cxi - cxj) / wi, 1e-3f));
        float a1 = 100.0f * logf(fmaxf(fabsf(cyi - cyj) / hi, 1e-3f));
        float a[2] = {a0, a1};

        float acc[8];
        #pragma unroll
        for (int h = 0; h < 8; h++) acc[h] = sbG[h];

        // dx, dy: 16 software sincos
        #pragma unroll
        for (int f = 0; f < 2; f++) {
            #pragma unroll
            for (int r = 0; r < 8; r++) {
                float s, c;
                sincosf(a[f] * dm[r], &s, &c);
                const int t = f*8 + r;
                #pragma unroll
                for (int h = 0; h < 8; h++)
                    acc[h] += s * sWGs[t][h] + c * sWGc[t][h];
            }
        }

        // dw, dh: exact angle-addition from j-side table (0 sincos)
        const float* tj = tblb + (long)j*32;
        float4 jt[8];
        #pragma unroll
        for (int u = 0; u < 8; u++) jt[u] = *(const float4*)(tj + u*4);
        const float* jf = (const float*)jt;   // [sw8|cw8|sh8|ch8]
        #pragma unroll
        for (int st = 0; st < 16; st++) {
            int feat = st >> 3, r = st & 7;
            float sj = jf[feat*16 + r];
            float cj = jf[feat*16 + 8 + r];
            #pragma unroll
            for (int h = 0; h < 8; h++)
                acc[h] += cj * sP[st][h] + sj * sQ[st][h];
        }

        #pragma unroll
        for (int h = 0; h < 8; h++) {
            float wg = fmaxf(acc[h], 1e-6f);
            outb[(long)h*NTOK*NTOK + j] = logf(wg);
        }
    }
}

// =====================================================================
// TF32 GEMM core: 64x64 tile, 128 threads, single-buffer smem +
// register prefetch, stride-72 conflict-free. K range [kbeg, kend).
// =====================================================================
template<typename WriteFn>
__device__ __forceinline__ void gemm64_core(
    const float* __restrict__ X, const float* __restrict__ W,
    int m0, int n0, int kbeg, int kend, WriteFn&& write)
{
    __shared__ float As[16][72];
    __shared__ float Bs[16][72];

    const int tid = threadIdx.x;
    const int lm = tid >> 1;
    const int lk = (tid & 1) * 8;

    const float* Aptr = X + (long)(m0 + lm)*512 + lk;
    const float* Bptr = W + (long)(n0 + lm)*512 + lk;

    float4 xa = *(const float4*)(Aptr + kbeg);
    float4 xb = *(const float4*)(Aptr + kbeg + 4);
    float4 wa = *(const float4*)(Bptr + kbeg);
    float4 wb = *(const float4*)(Bptr + kbeg + 4);

    const int w    = tid >> 5;
    const int wm   = (w & 1) * 32;
    const int wn2  = (w >> 1) * 32;
    const int lane = tid & 31;
    const int lr   = lane >> 2;
    const int lc   = lane & 3;

    float acc[2][4][4];
    #pragma unroll
    for (int mi = 0; mi < 2; mi++)
        #pragma unroll
        for (int ni = 0; ni < 4; ni++)
            #pragma unroll
            for (int q = 0; q < 4; q++) acc[mi][ni][q] = 0.0f;

    for (int k0 = kbeg; k0 < kend; k0 += 16) {
        As[lk+0][lm]=f2tf32f(xa.x); As[lk+1][lm]=f2tf32f(xa.y);
        As[lk+2][lm]=f2tf32f(xa.z); As[lk+3][lm]=f2tf32f(xa.w);
        As[lk+4][lm]=f2tf32f(xb.x); As[lk+5][lm]=f2tf32f(xb.y);
        As[lk+6][lm]=f2tf32f(xb.z); As[lk+7][lm]=f2tf32f(xb.w);
        Bs[lk+0][lm]=f2tf32f(wa.x); Bs[lk+1][lm]=f2tf32f(wa.y);
        Bs[lk+2][lm]=f2tf32f(wa.z); Bs[lk+3][lm]=f2tf32f(wa.w);
        Bs[lk+4][lm]=f2tf32f(wb.x); Bs[lk+5][lm]=f2tf32f(wb.y);
        Bs[lk+6][lm]=f2tf32f(wb.z); Bs[lk+7][lm]=f2tf32f(wb.w);
        __syncthreads();

        if (k0 + 16 < kend) {
            xa = *(const float4*)(Aptr + k0 + 16);
            xb = *(const float4*)(Aptr + k0 + 20);
            wa = *(const float4*)(Bptr + k0 + 16);
            wb = *(const float4*)(Bptr + k0 + 20);
        }

        #pragma unroll
        for (int ks = 0; ks < 2; ks++) {
            const int kb = ks * 8;
            unsigned afr[2][4];
            #pragma unroll
            for (int mi = 0; mi < 2; mi++) {
                const int mrow = wm + 16*mi;
                afr[mi][0] = __float_as_uint(As[kb + lc    ][mrow + lr    ]);
                afr[mi][1] = __float_as_uint(As[kb + lc    ][mrow + lr + 8]);
                afr[mi][2] = __float_as_uint(As[kb + lc + 4][mrow + lr    ]);
                afr[mi][3] = __float_as_uint(As[kb + lc + 4][mrow + lr + 8]);
            }
            unsigned bfr[4][2];
            #pragma unroll
            for (int ni = 0; ni < 4; ni++) {
                const int ncol = wn2 + 8*ni;
                bfr[ni][0] = __float_as_uint(Bs[kb + lc    ][ncol + lr]);
                bfr[ni][1] = __float_as_uint(Bs[kb + lc + 4][ncol + lr]);
            }
            #pragma unroll
            for (int mi = 0; mi < 2; mi++)
                #pragma unroll
                for (int ni = 0; ni < 4; ni++)
                    mma_tf32(acc[mi][ni][0], acc[mi][ni][1],
                             acc[mi][ni][2], acc[mi][ni][3],
                             afr[mi][0], afr[mi][1], afr[mi][2], afr[mi][3],
                             bfr[ni][0], bfr[ni][1]);
        }
        __syncthreads();
    }

    #pragma unroll
    for (int mi = 0; mi < 2; mi++) {
        #pragma unroll
        for (int ni = 0; ni < 4; ni++) {
            const int row = wm + 16*mi + lr;
            const int col = wn2 + 8*ni + 2*lc;
            write(row,     col, acc[mi][ni][0], acc[mi][ni][1]);
            write(row + 8, col, acc[mi][ni][2], acc[mi][ni][3]);
        }
    }
}

// ---- fused QKV projection (head-split write) ----
__global__ void __launch_bounds__(128) qkv_kernel(
    const float* __restrict__ Xq, const float* __restrict__ Xk, const float* __restrict__ Xv,
    const float* __restrict__ Wq, const float* __restrict__ Wk, const float* __restrict__ Wv,
    const float* __restrict__ bq, const float* __restrict__ bk, const float* __restrict__ bv)
{
    const int z = blockIdx.z;
    const float* X    = (z == 0) ? Xq : (z == 1) ? Xk : Xv;
    const float* W    = (z == 0) ? Wq : (z == 1) ? Wk : Wv;
    const float* bias = (z == 0) ? bq : (z == 1) ? bk : bv;
    float*       Y    = (z == 0) ? g_Q : (z == 1) ? g_K : g_V;

    const int m0 = blockIdx.y * 64;
    const int n0 = blockIdx.x * 64;
    const int h  = n0 >> 6;

    gemm64_core(X, W, m0, n0, 0, 512,
        [&](int row, int col, float v0, float v1) {
            int m = m0 + row;
            int b = m >> 9, n = m & 511;
            float2 r;
            r.x = v0 + bias[n0 + col];
            r.y = v1 + bias[n0 + col + 1];
            *(float2*)(Y + (((long)(b*NH + h)*NTOK + n)*DKH) + col) = r;
        });
}

// ---- zero-init for split-K accumulation target ----
__global__ void zero_kernel(float4* __restrict__ p, int n4)
{
    int i = blockIdx.x * blockDim.x + threadIdx.x;
    if (i < n4) p[i] = make_float4(0.f, 0.f, 0.f, 0.f);
}

// ---- output projection, split-K=2 (atomicAdd; 2 adds/elem = commutative,
//      hence bit-deterministic) ----
__global__ void __launch_bounds__(128) oproj_kernel(
    const float* __restrict__ W, const float* __restrict__ bias,
    float* __restrict__ Yout)
{
    const int m0 = blockIdx.y * 64;
    const int n0 = blockIdx.x * 64;
    const int z  = blockIdx.z;           // k-half
    const int kbeg = z * 256, kend = kbeg + 256;

    gemm64_core(g_CTX, W, m0, n0, kbeg, kend,
        [&](int row, int col, float v0, float v1) {
            float b0 = (z == 0) ? bias[n0 + col]     : 0.0f;
            float b1 = (z == 0) ? bias[n0 + col + 1] : 0.0f;
            float* p = Yout + (long)(m0 + row)*512 + n0 + col;
            atomicAdd(p,     v0 + b0);
            atomicAdd(p + 1, v1 + b1);
        });
}

// =====================================================================
// Kernel 3: flash attention, TF32 mma, latency-hidden staging.
// (unchanged from the verified 228-229us builds)
// =====================================================================
#define QS_STRIDE 68
#define KS_STRIDE 72

__global__ void __launch_bounds__(128) attn_kernel()
{
    extern __shared__ float sm[];
    float* Qs = sm;                      // [64][68]  m-major (tf32, x0.125)
    float* Ks = Qs + 64*QS_STRIDE;       // [64][72]  k-major
    float* Vs = Ks + 64*KS_STRIDE;       // [64][72]  token-major
    float* Ps = Vs + 64*KS_STRIDE;       // [64][68]  m-major

    const int tid  = threadIdx.x;
    const int lane = tid & 31;
    const int w    = tid >> 5;
    const int wm   = w * 16;
    const int lr   = lane >> 2;
    const int lc   = lane & 3;

    const int bh = blockIdx.x;
    const int q0 = blockIdx.y * 64;

    const float* Qg = g_Q   + (long)bh*NTOK*DKH + (long)q0*DKH;
    const float* Kg = g_K   + (long)bh*NTOK*DKH;
    const float* Vg = g_V   + (long)bh*NTOK*DKH;
    const float* Bg = g_BIAS + (long)bh*NTOK*NTOK + (long)q0*NTOK;

    const int n  = tid >> 1;
    const int kq = (tid & 1) * 32;

    {
        const float* src = Qg + n*64 + kq;
        #pragma unroll
        for (int u = 0; u < 8; u++) {
            float4 v = *(const float4*)(src + u*4);
            Qs[n*QS_STRIDE + kq + u*4 + 0] = f2tf32f(v.x * 0.125f);
            Qs[n*QS_STRIDE + kq + u*4 + 1] = f2tf32f(v.y * 0.125f);
            Qs[n*QS_STRIDE + kq + u*4 + 2] = f2tf32f(v.z * 0.125f);
            Qs[n*QS_STRIDE + kq + u*4 + 3] = f2tf32f(v.w * 0.125f);
        }
    }

    float4 kreg[8];
    {
        const float* srcK = Kg + (long)n*64 + kq;
        #pragma unroll
        for (int u = 0; u < 8; u++) kreg[u] = *(const float4*)(srcK + u*4);
    }

    float m_i[2] = {-1e30f, -1e30f};
    float l_i[2] = {0.0f, 0.0f};
    float o[8][4];
    #pragma unroll
    for (int d = 0; d < 8; d++)
        #pragma unroll
        for (int q = 0; q < 4; q++) o[d][q] = 0.0f;

    for (int t = 0; t < 8; t++) {
        __syncthreads();

        #pragma unroll
        for (int u = 0; u < 8; u++) {
            Ks[(kq+u*4+0)*KS_STRIDE + n] = f2tf32f(kreg[u].x);
            Ks[(kq+u*4+1)*KS_STRIDE + n] = f2tf32f(kreg[u].y);
            Ks[(kq+u*4+2)*KS_STRIDE + n] = f2tf32f(kreg[u].z);
            Ks[(kq+u*4+3)*KS_STRIDE + n] = f2tf32f(kreg[u].w);
        }

        if (t < 7) {
            const float* srcK = Kg + (long)((t+1)*64 + n)*64 + kq;
            #pragma unroll
            for (int u = 0; u < 8; u++) kreg[u] = *(const float4*)(srcK + u*4);
        }

        float4 vreg[8];
        {
            const float* srcV = Vg + (long)(t*64 + n)*64 + kq;
            #pragma unroll
            for (int u = 0; u < 8; u++) vreg[u] = *(const float4*)(srcV + u*4);
        }

        float2 breg0[8], breg1[8];
        {
            const float* brow0 = Bg + (long)(wm+lr  )*512 + t*64;
            const float* brow1 = Bg + (long)(wm+lr+8)*512 + t*64;
            #pragma unroll
            for (int nc = 0; nc < 8; nc++) {
                breg0[nc] = *(const float2*)(brow0 + 8*nc + 2*lc);
                breg1[nc] = *(const float2*)(brow1 + 8*nc + 2*lc);
            }
        }
        __syncthreads();

        float sacc[8][4];
        #pragma unroll
        for (int nc = 0; nc < 8; nc++)
            #pragma unroll
            for (int q = 0; q < 4; q++) sacc[nc][q] = 0.0f;

        #pragma unroll
        for (int ks = 0; ks < 8; ks++) {
            const int kb = ks * 8;
            unsigned a0 = __float_as_uint(Qs[(wm+lr  )*QS_STRIDE + kb + lc    ]);
            unsigned a1 = __float_as_uint(Qs[(wm+lr+8)*QS_STRIDE + kb + lc    ]);
            unsigned a2 = __float_as_uint(Qs[(wm+lr  )*QS_STRIDE + kb + lc + 4]);
            unsigned a3 = __float_as_uint(Qs[(wm+lr+8)*QS_STRIDE + kb + lc + 4]);
            #pragma unroll
            for (int nc = 0; nc < 8; nc++) {
                unsigned b0 = __float_as_uint(Ks[(kb+lc  )*KS_STRIDE + 8*nc + lr]);
                unsigned b1 = __float_as_uint(Ks[(kb+lc+4)*KS_STRIDE + 8*nc + lr]);
                mma_tf32(sacc[nc][0], sacc[nc][1], sacc[nc][2], sacc[nc][3],
                         a0, a1, a2, a3, b0, b1);
            }
        }

        #pragma unroll
        for (int u = 0; u < 8; u++) {
            float4 cv;
            cv.x = f2tf32f(vreg[u].x); cv.y = f2tf32f(vreg[u].y);
            cv.z = f2tf32f(vreg[u].z); cv.w = f2tf32f(vreg[u].w);
            *(float4*)&Vs[n*KS_STRIDE + kq + u*4] = cv;
        }

        #pragma unroll
        for (int nc = 0; nc < 8; nc++) {
            sacc[nc][0] += breg0[nc].x; sacc[nc][1] += breg0[nc].y;
            sacc[nc][2] += breg1[nc].x; sacc[nc][3] += breg1[nc].y;
        }

        #pragma unroll
        for (int i = 0; i < 2; i++) {
            float tm = -1e30f;
            #pragma unroll
            for (int nc = 0; nc < 8; nc++)
                tm = fmaxf(tm, fmaxf(sacc[nc][2*i], sacc[nc][2*i+1]));
            tm = fmaxf(tm, __shfl_xor_sync(0xffffffffu, tm, 1));
            tm = fmaxf(tm, __shfl_xor_sync(0xffffffffu, tm, 2));
            float mnew = fmaxf(m_i[i], tm);
            float scale = __expf(m_i[i] - mnew);
            m_i[i] = mnew;

            float s = 0.0f;
            #pragma unroll
            for (int nc = 0; nc < 8; nc++) {
                float p0 = __expf(sacc[nc][2*i]   - mnew);
                float p1 = __expf(sacc[nc][2*i+1] - mnew);
                sacc[nc][2*i]   = p0;
                sacc[nc][2*i+1] = p1;
                s += p0 + p1;
            }
            s += __shfl_xor_sync(0xffffffffu, s, 1);
            s += __shfl_xor_sync(0xffffffffu, s, 2);
            l_i[i] = l_i[i]*scale + s;

            #pragma unroll
            for (int d = 0; d < 8; d++) {
                o[d][2*i]   *= scale;
                o[d][2*i+1] *= scale;
            }
        }

        #pragma unroll
        for (int nc = 0; nc < 8; nc++) {
            float2 p0, p1;
            p0.x = f2tf32f(sacc[nc][0]); p0.y = f2tf32f(sacc[nc][1]);
            p1.x = f2tf32f(sacc[nc][2]); p1.y = f2tf32f(sacc[nc][3]);
            *(float2*)&Ps[(wm+lr  )*QS_STRIDE + 8*nc + 2*lc] = p0;
            *(float2*)&Ps[(wm+lr+8)*QS_STRIDE + 8*nc + 2*lc] = p1;
        }
        __syncthreads();

        #pragma unroll
        for (int ks = 0; ks < 8; ks++) {
            const int kb = ks * 8;
            unsigned a0 = __float_as_uint(Ps[(wm+lr  )*QS_STRIDE + kb + lc    ]);
            unsigned a1 = __float_as_uint(Ps[(wm+lr+8)*QS_STRIDE + kb + lc    ]);
            unsigned a2 = __float_as_uint(Ps[(wm+lr  )*QS_STRIDE + kb + lc + 4]);
            unsigned a3 = __float_as_uint(Ps[(wm+lr+8)*QS_STRIDE + kb + lc + 4]);
            #pragma unroll
            for (int dc = 0; dc < 8; dc++) {
                unsigned b0 = __float_as_uint(Vs[(kb+lc  )*KS_STRIDE + 8*dc + lr]);
                unsigned b1 = __float_as_uint(Vs[(kb+lc+4)*KS_STRIDE + 8*dc + lr]);
                mma_tf32(o[dc][0], o[dc][1], o[dc][2], o[dc][3],
                         a0, a1, a2, a3, b0, b1);
            }
        }
    }

    const int b = bh >> 3, h = bh & 7;
    const float inv0 = 1.0f / l_i[0];
    const float inv1 = 1.0f / l_i[1];
    float* ctx0 = g_CTX + ((long)(b*NTOK + q0 + wm + lr    ))*512 + h*64;
    float* ctx1 = g_CTX + ((long)(b*NTOK + q0 + wm + lr + 8))*512 + h*64;
    #pragma unroll
    for (int dc = 0; dc < 8; dc++) {
        float2 r0, r1;
        r0.x = o[dc][0]*inv0; r0.y = o[dc][1]*inv0;
        r1.x = o[dc][2]*inv1; r1.y = o[dc][3]*inv1;
        *(float2*)(ctx0 + 8*dc + 2*lc) = r0;
        *(float2*)(ctx1 + 8*dc + 2*lc) = r1;
    }
}

// =====================================================================
// launch
// =====================================================================
extern "C" void kernel_launch(void* const* d_in, const int* in_sizes, int n_in,
                              void* d_out, int out_size)
{
    const float* in_q  = (const float*)d_in[0];
    const float* in_k  = (const float*)d_in[1];
    const float* in_v  = (const float*)d_in[2];
    const float* box   = (const float*)d_in[3];
    const float* Wq    = (const float*)d_in[4];
    const float* bq    = (const float*)d_in[5];
    const float* Wk    = (const float*)d_in[6];
    const float* bk    = (const float*)d_in[7];
    const float* Wv    = (const float*)d_in[8];
    const float* bv    = (const float*)d_in[9];
    const float* Wo    = (const float*)d_in[10];
    const float* bo    = (const float*)d_in[11];
    const float* WG    = (const float*)d_in[12];
    const float* bG    = (const float*)d_in[13];
    float* out = (float*)d_out;

    const int ATTN_SMEM = (2*64*QS_STRIDE + 2*64*KS_STRIDE) * (int)sizeof(float); // 71680
    cudaFuncSetAttribute(attn_kernel, cudaFuncAttributeMaxDynamicSharedMemorySize, ATTN_SMEM);

    // per-box table (software sincos), then geometry bias (half the sincos)
    geom_table_kernel<<<(BATCH*NTOK + 255)/256, 256>>>(box);
    geom_kernel<<<dim3(NTOK, BATCH), 256>>>(box, WG, bG);

    // fused Q/K/V projections (tf32 tensor cores)
    qkv_kernel<<<dim3(512/64, 2048/64, 3), 128>>>(in_q, in_k, in_v,
                                                  Wq, Wk, Wv, bq, bk, bv);

    // attention (tf32 tensor cores, latency-hidden staging)
    attn_kernel<<<dim3(BATCH*NH, NTOK/64), 128, ATTN_SMEM>>>();

    // output projection -> d_out (split-K=2, zero-init + atomic accumulate)
    {
        const int n4 = (BATCH*NTOK*DMODEL) / 4;   // 262144 float4
        zero_kernel<<<(n4 + 255)/256, 256>>>((float4*)out, n4);
        oproj_kernel<<<dim3(512/64, 2048/64, 2), 128>>>(Wo, bo, out);
    }
}

// round 14
// speedup vs baseline: 1.6388x; 1.1972x over previous
#include <cuda_runtime.h>
#include <math.h>

#define BATCH   4
#define NTOK    512
#define DMODEL  512
#define NH      8
#define DKH     64

// ---------------- device scratch (no allocations allowed) ----------------
__device__ float g_Q[BATCH*NH*NTOK*DKH];     // 4 MB
__device__ float g_K[BATCH*NH*NTOK*DKH];     // 4 MB
__device__ float g_V[BATCH*NH*NTOK*DKH];     // 4 MB
__device__ float g_BIAS[BATCH*NH*NTOK*NTOK]; // 32 MB
__device__ float g_CTX[BATCH*NTOK*DMODEL];   // 4 MB

// ---------------- helpers ----------------
__device__ __forceinline__ unsigned f2tf32(float x) {
    unsigned b;
    asm("cvt.rna.tf32.f32 %0, %1;" : "=r"(b) : "f"(x));
    return b;
}
__device__ __forceinline__ float f2tf32f(float x) {
    return __uint_as_float(f2tf32(x));
}

__device__ __forceinline__ void mma_tf32(float& c0, float& c1, float& c2, float& c3,
                                         unsigned a0, unsigned a1, unsigned a2, unsigned a3,
                                         unsigned b0, unsigned b1) {
    asm volatile("mma.sync.aligned.m16n8k8.row.col.f32.tf32.tf32.f32 "
                 "{%0,%1,%2,%3}, {%4,%5,%6,%7}, {%8,%9}, {%0,%1,%2,%3};"
                 : "+f"(c0), "+f"(c1), "+f"(c2), "+f"(c3)
                 : "r"(a0), "r"(a1), "r"(a2), "r"(a3), "r"(b0), "r"(b1));
}

// =====================================================================
// Kernel 1: geometry bias.  grid (NTOK, BATCH), 256 threads.
// EXACT round-7 (228.4us verified) version: software sincosf/logf.
// DO NOT TOUCH: MUFU and table variants both regressed.
// =====================================================================
__global__ void geom_kernel(const float* __restrict__ box,
                            const float* __restrict__ WG,
                            const float* __restrict__ bG)
{
    __shared__ float sWGs[32][8];
    __shared__ float sWGc[32][8];
    __shared__ float sbG[8];

    const int b = blockIdx.y;
    const int i = blockIdx.x;
    const int tid = threadIdx.x;

    for (int e = tid; e < 512; e += blockDim.x) {
        int h = e >> 6, g = e & 63;
        float v = WG[e];
        if (g < 32) sWGs[g][h] = v;
        else        sWGc[g - 32][h] = v;
    }
    if (tid < 8) sbG[tid] = bG[tid];

    const float4 bi = *(const float4*)(box + ((long)b*NTOK + i)*4);
    const float cxi = 0.5f*(bi.x + bi.z);
    const float cyi = 0.5f*(bi.y + bi.w);
    const float wi  = bi.z - bi.x + 1.0f;
    const float hi  = bi.w - bi.y + 1.0f;
    const float lwi = logf(wi);
    const float lhi = logf(hi);
    __syncthreads();

    const float dm[8] = {1.0f, 0.4216965034f, 0.1778279410f, 0.0749894209f,
                         0.0316227766f, 0.0133352143f, 0.0056234133f, 0.0023713737f};

    float* outb = g_BIAS + ((long)b*NH*NTOK + i)*NTOK;

    for (int j = tid; j < NTOK; j += blockDim.x) {
        float4 bj = *(const float4*)(box + ((long)b*NTOK + j)*4);
        float cxj = 0.5f*(bj.x + bj.z);
        float cyj = 0.5f*(bj.y + bj.w);
        float wj  = bj.z - bj.x + 1.0f;
        float hj  = bj.w - bj.y + 1.0f;

        float a0 = 100.0f * logf(fmaxf(fabsf(cxi - cxj) / wi, 1e-3f));
        float a1 = 100.0f * logf(fmaxf(fabsf(cyi - cyj) / hi, 1e-3f));
        float a2 = 100.0f * (lwi - logf(wj));
        float a3 = 100.0f * (lhi - logf(hj));
        float a[4] = {a0, a1, a2, a3};

        float acc[8];
        #pragma unroll
        for (int h = 0; h < 8; h++) acc[h] = sbG[h];

        #pragma unroll
        for (int f = 0; f < 4; f++) {
            #pragma unroll
            for (int r = 0; r < 8; r++) {
                float s, c;
                sincosf(a[f] * dm[r], &s, &c);
                const int t = f*8 + r;
                #pragma unroll
                for (int h = 0; h < 8; h++)
                    acc[h] += s * sWGs[t][h] + c * sWGc[t][h];
            }
        }
        #pragma unroll
        for (int h = 0; h < 8; h++) {
            float wg = fmaxf(acc[h], 1e-6f);
            outb[(long)h*NTOK*NTOK + j] = logf(wg);
        }
    }
}

// =====================================================================
// TF32 GEMM core, BK=32: 64x64 tile, 128 threads, single-buffer smem +
// register prefetch, stride-72 conflict-free. 16 iterations, half the
// barriers of the BK=16 version. K fixed [0, 512).
// =====================================================================
template<typename WriteFn>
__device__ __forceinline__ void gemm64_core(
    const float* __restrict__ X, const float* __restrict__ W,
    int m0, int n0, WriteFn&& write)
{
    __shared__ float As[32][72];
    __shared__ float Bs[32][72];

    const int tid = threadIdx.x;
    const int lm = tid >> 1;           // row 0..63
    const int lk = (tid & 1) * 16;     // k offset 0 or 16

    const float* Aptr = X + (long)(m0 + lm)*512 + lk;
    const float* Bptr = W + (long)(n0 + lm)*512 + lk;

    float4 xa[4], wa[4];
    #pragma unroll
    for (int u = 0; u < 4; u++) {
        xa[u] = *(const float4*)(Aptr + u*4);
        wa[u] = *(const float4*)(Bptr + u*4);
    }

    const int w    = tid >> 5;
    const int wm   = (w & 1) * 32;
    const int wn2  = (w >> 1) * 32;
    const int lane = tid & 31;
    const int lr   = lane >> 2;
    const int lc   = lane & 3;

    float acc[2][4][4];
    #pragma unroll
    for (int mi = 0; mi < 2; mi++)
        #pragma unroll
        for (int ni = 0; ni < 4; ni++)
            #pragma unroll
            for (int q = 0; q < 4; q++) acc[mi][ni][q] = 0.0f;

    for (int k0 = 0; k0 < 512; k0 += 32) {
        #pragma unroll
        for (int u = 0; u < 4; u++) {
            As[lk+u*4+0][lm]=f2tf32f(xa[u].x); As[lk+u*4+1][lm]=f2tf32f(xa[u].y);
            As[lk+u*4+2][lm]=f2tf32f(xa[u].z); As[lk+u*4+3][lm]=f2tf32f(xa[u].w);
            Bs[lk+u*4+0][lm]=f2tf32f(wa[u].x); Bs[lk+u*4+1][lm]=f2tf32f(wa[u].y);
            Bs[lk+u*4+2][lm]=f2tf32f(wa[u].z); Bs[lk+u*4+3][lm]=f2tf32f(wa[u].w);
        }
        __syncthreads();

        if (k0 + 32 < 512) {
            #pragma unroll
            for (int u = 0; u < 4; u++) {
                xa[u] = *(const float4*)(Aptr + k0 + 32 + u*4);
                wa[u] = *(const float4*)(Bptr + k0 + 32 + u*4);
            }
        }

        #pragma unroll
        for (int ks = 0; ks < 4; ks++) {
            const int kb = ks * 8;
            unsigned afr[2][4];
            #pragma unroll
            for (int mi = 0; mi < 2; mi++) {
                const int mrow = wm + 16*mi;
                afr[mi][0] = __float_as_uint(As[kb + lc    ][mrow + lr    ]);
                afr[mi][1] = __float_as_uint(As[kb + lc    ][mrow + lr + 8]);
                afr[mi][2] = __float_as_uint(As[kb + lc + 4][mrow + lr    ]);
                afr[mi][3] = __float_as_uint(As[kb + lc + 4][mrow + lr + 8]);
            }
            unsigned bfr[4][2];
            #pragma unroll
            for (int ni = 0; ni < 4; ni++) {
                const int ncol = wn2 + 8*ni;
                bfr[ni][0] = __float_as_uint(Bs[kb + lc    ][ncol + lr]);
                bfr[ni][1] = __float_as_uint(Bs[kb + lc + 4][ncol + lr]);
            }
            #pragma unroll
            for (int mi = 0; mi < 2; mi++)
                #pragma unroll
                for (int ni = 0; ni < 4; ni++)
                    mma_tf32(acc[mi][ni][0], acc[mi][ni][1],
                             acc[mi][ni][2], acc[mi][ni][3],
                             afr[mi][0], afr[mi][1], afr[mi][2], afr[mi][3],
                             bfr[ni][0], bfr[ni][1]);
        }
        __syncthreads();
    }

    #pragma unroll
    for (int mi = 0; mi < 2; mi++) {
        #pragma unroll
        for (int ni = 0; ni < 4; ni++) {
            const int row = wm + 16*mi + lr;
            const int col = wn2 + 8*ni + 2*lc;
            write(row,     col, acc[mi][ni][0], acc[mi][ni][1]);
            write(row + 8, col, acc[mi][ni][2], acc[mi][ni][3]);
        }
    }
}

// ---- fused QKV projection (head-split write) ----
__global__ void __launch_bounds__(128) qkv_kernel(
    const float* __restrict__ Xq, const float* __restrict__ Xk, const float* __restrict__ Xv,
    const float* __restrict__ Wq, const float* __restrict__ Wk, const float* __restrict__ Wv,
    const float* __restrict__ bq, const float* __restrict__ bk, const float* __restrict__ bv)
{
    const int z = blockIdx.z;
    const float* X    = (z == 0) ? Xq : (z == 1) ? Xk : Xv;
    const float* W    = (z == 0) ? Wq : (z == 1) ? Wk : Wv;
    const float* bias = (z == 0) ? bq : (z == 1) ? bk : bv;
    float*       Y    = (z == 0) ? g_Q : (z == 1) ? g_K : g_V;

    const int m0 = blockIdx.y * 64;
    const int n0 = blockIdx.x * 64;
    const int h  = n0 >> 6;

    gemm64_core(X, W, m0, n0,
        [&](int row, int col, float v0, float v1) {
            int m = m0 + row;
            int b = m >> 9, n = m & 511;
            float2 r;
            r.x = v0 + bias[n0 + col];
            r.y = v1 + bias[n0 + col + 1];
            *(float2*)(Y + (((long)(b*NH + h)*NTOK + n)*DKH) + col) = r;
        });
}

// ---- output projection (plain full-K write) ----
__global__ void __launch_bounds__(128) oproj_kernel(
    const float* __restrict__ W, const float* __restrict__ bias,
    float* __restrict__ Yout)
{
    const int m0 = blockIdx.y * 64;
    const int n0 = blockIdx.x * 64;

    gemm64_core(g_CTX, W, m0, n0,
        [&](int row, int col, float v0, float v1) {
            float2 r;
            r.x = v0 + bias[n0 + col];
            r.y = v1 + bias[n0 + col + 1];
            *(float2*)(Yout + (long)(m0 + row)*512 + n0 + col) = r;
        });
}

// =====================================================================
// Kernel 3: flash attention, TF32 mma, latency-hidden staging.
// EXACT round-7 (228.4us verified) version.
// =====================================================================
#define QS_STRIDE 68
#define KS_STRIDE 72

__global__ void __launch_bounds__(128) attn_kernel()
{
    extern __shared__ float sm[];
    float* Qs = sm;                      // [64][68]  m-major (tf32, x0.125)
    float* Ks = Qs + 64*QS_STRIDE;       // [64][72]  k-major
    float* Vs = Ks + 64*KS_STRIDE;       // [64][72]  token-major
    float* Ps = Vs + 64*KS_STRIDE;       // [64][68]  m-major

    const int tid  = threadIdx.x;
    const int lane = tid & 31;
    const int w    = tid >> 5;
    const int wm   = w * 16;
    const int lr   = lane >> 2;
    const int lc   = lane & 3;

    const int bh = blockIdx.x;
    const int q0 = blockIdx.y * 64;

    const float* Qg = g_Q   + (long)bh*NTOK*DKH + (long)q0*DKH;
    const float* Kg = g_K   + (long)bh*NTOK*DKH;
    const float* Vg = g_V   + (long)bh*NTOK*DKH;
    const float* Bg = g_BIAS + (long)bh*NTOK*NTOK + (long)q0*NTOK;

    const int n  = tid >> 1;
    const int kq = (tid & 1) * 32;

    {
        const float* src = Qg + n*64 + kq;
        #pragma unroll
        for (int u = 0; u < 8; u++) {
            float4 v = *(const float4*)(src + u*4);
            Qs[n*QS_STRIDE + kq + u*4 + 0] = f2tf32f(v.x * 0.125f);
            Qs[n*QS_STRIDE + kq + u*4 + 1] = f2tf32f(v.y * 0.125f);
            Qs[n*QS_STRIDE + kq + u*4 + 2] = f2tf32f(v.z * 0.125f);
            Qs[n*QS_STRIDE + kq + u*4 + 3] = f2tf32f(v.w * 0.125f);
        }
    }

    float4 kreg[8];
    {
        const float* srcK = Kg + (long)n*64 + kq;
        #pragma unroll
        for (int u = 0; u < 8; u++) kreg[u] = *(const float4*)(srcK + u*4);
    }

    float m_i[2] = {-1e30f, -1e30f};
    float l_i[2] = {0.0f, 0.0f};
    float o[8][4];
    #pragma unroll
    for (int d = 0; d < 8; d++)
        #pragma unroll
        for (int q = 0; q < 4; q++) o[d][q] = 0.0f;

    for (int t = 0; t < 8; t++) {
        __syncthreads();

        #pragma unroll
        for (int u = 0; u < 8; u++) {
            Ks[(kq+u*4+0)*KS_STRIDE + n] = f2tf32f(kreg[u].x);
            Ks[(kq+u*4+1)*KS_STRIDE + n] = f2tf32f(kreg[u].y);
            Ks[(kq+u*4+2)*KS_STRIDE + n] = f2tf32f(kreg[u].z);
            Ks[(kq+u*4+3)*KS_STRIDE + n] = f2tf32f(kreg[u].w);
        }

        if (t < 7) {
            const float* srcK = Kg + (long)((t+1)*64 + n)*64 + kq;
            #pragma unroll
            for (int u = 0; u < 8; u++) kreg[u] = *(const float4*)(srcK + u*4);
        }

        float4 vreg[8];
        {
            const float* srcV = Vg + (long)(t*64 + n)*64 + kq;
            #pragma unroll
            for (int u = 0; u < 8; u++) vreg[u] = *(const float4*)(srcV + u*4);
        }

        float2 breg0[8], breg1[8];
        {
            const float* brow0 = Bg + (long)(wm+lr  )*512 + t*64;
            const float* brow1 = Bg + (long)(wm+lr+8)*512 + t*64;
            #pragma unroll
            for (int nc = 0; nc < 8; nc++) {
                breg0[nc] = *(const float2*)(brow0 + 8*nc + 2*lc);
                breg1[nc] = *(const float2*)(brow1 + 8*nc + 2*lc);
            }
        }
        __syncthreads();

        float sacc[8][4];
        #pragma unroll
        for (int nc = 0; nc < 8; nc++)
            #pragma unroll
            for (int q = 0; q < 4; q++) sacc[nc][q] = 0.0f;

        #pragma unroll
        for (int ks = 0; ks < 8; ks++) {
            const int kb = ks * 8;
            unsigned a0 = __float_as_uint(Qs[(wm+lr  )*QS_STRIDE + kb + lc    ]);
            unsigned a1 = __float_as_uint(Qs[(wm+lr+8)*QS_STRIDE + kb + lc    ]);
            unsigned a2 = __float_as_uint(Qs[(wm+lr  )*QS_STRIDE + kb + lc + 4]);
            unsigned a3 = __float_as_uint(Qs[(wm+lr+8)*QS_STRIDE + kb + lc + 4]);
            #pragma unroll
            for (int nc = 0; nc < 8; nc++) {
                unsigned b0 = __float_as_uint(Ks[(kb+lc  )*KS_STRIDE + 8*nc + lr]);
                unsigned b1 = __float_as_uint(Ks[(kb+lc+4)*KS_STRIDE + 8*nc + lr]);
                mma_tf32(sacc[nc][0], sacc[nc][1], sacc[nc][2], sacc[nc][3],
                         a0, a1, a2, a3, b0, b1);
            }
        }

        #pragma unroll
        for (int u = 0; u < 8; u++) {
            float4 cv;
            cv.x = f2tf32f(vreg[u].x); cv.y = f2tf32f(vreg[u].y);
            cv.z = f2tf32f(vreg[u].z); cv.w = f2tf32f(vreg[u].w);
            *(float4*)&Vs[n*KS_STRIDE + kq + u*4] = cv;
        }

        #pragma unroll
        for (int nc = 0; nc < 8; nc++) {
            sacc[nc][0] += breg0[nc].x; sacc[nc][1] += breg0[nc].y;
            sacc[nc][2] += breg1[nc].x; sacc[nc][3] += breg1[nc].y;
        }

        #pragma unroll
        for (int i = 0; i < 2; i++) {
            float tm = -1e30f;
            #pragma unroll
            for (int nc = 0; nc < 8; nc++)
                tm = fmaxf(tm, fmaxf(sacc[nc][2*i], sacc[nc][2*i+1]));
            tm = fmaxf(tm, __shfl_xor_sync(0xffffffffu, tm, 1));
            tm = fmaxf(tm, __shfl_xor_sync(0xffffffffu, tm, 2));
            float mnew = fmaxf(m_i[i], tm);
            float scale = __expf(m_i[i] - mnew);
            m_i[i] = mnew;

            float s = 0.0f;
            #pragma unroll
            for (int nc = 0; nc < 8; nc++) {
                float p0 = __expf(sacc[nc][2*i]   - mnew);
                float p1 = __expf(sacc[nc][2*i+1] - mnew);
                sacc[nc][2*i]   = p0;
                sacc[nc][2*i+1] = p1;
                s += p0 + p1;
            }
            s += __shfl_xor_sync(0xffffffffu, s, 1);
            s += __shfl_xor_sync(0xffffffffu, s, 2);
            l_i[i] = l_i[i]*scale + s;

            #pragma unroll
            for (int d = 0; d < 8; d++) {
                o[d][2*i]   *= scale;
                o[d][2*i+1] *= scale;
            }
        }

        #pragma unroll
        for (int nc = 0; nc < 8; nc++) {
            float2 p0, p1;
            p0.x = f2tf32f(sacc[nc][0]); p0.y = f2tf32f(sacc[nc][1]);
            p1.x = f2tf32f(sacc[nc][2]); p1.y = f2tf32f(sacc[nc][3]);
            *(float2*)&Ps[(wm+lr  )*QS_STRIDE + 8*nc + 2*lc] = p0;
            *(float2*)&Ps[(wm+lr+8)*QS_STRIDE + 8*nc + 2*lc] = p1;
        }
        __syncthreads();

        #pragma unroll
        for (int ks = 0; ks < 8; ks++) {
            const int kb = ks * 8;
            unsigned a0 = __float_as_uint(Ps[(wm+lr  )*QS_STRIDE + kb + lc    ]);
            unsigned a1 = __float_as_uint(Ps[(wm+lr+8)*QS_STRIDE + kb + lc    ]);
            unsigned a2 = __float_as_uint(Ps[(wm+lr  )*QS_STRIDE + kb + lc + 4]);
            unsigned a3 = __float_as_uint(Ps[(wm+lr+8)*QS_STRIDE + kb + lc + 4]);
            #pragma unroll
            for (int dc = 0; dc < 8; dc++) {
                unsigned b0 = __float_as_uint(Vs[(kb+lc  )*KS_STRIDE + 8*dc + lr]);
                unsigned b1 = __float_as_uint(Vs[(kb+lc+4)*KS_STRIDE + 8*dc + lr]);
                mma_tf32(o[dc][0], o[dc][1], o[dc][2], o[dc][3],
                         a0, a1, a2, a3, b0, b1);
            }
        }
    }

    const int b = bh >> 3, h = bh & 7;
    const float inv0 = 1.0f / l_i[0];
    const float inv1 = 1.0f / l_i[1];
    float* ctx0 = g_CTX + ((long)(b*NTOK + q0 + wm + lr    ))*512 + h*64;
    float* ctx1 = g_CTX + ((long)(b*NTOK + q0 + wm + lr + 8))*512 + h*64;
    #pragma unroll
    for (int dc = 0; dc < 8; dc++) {
        float2 r0, r1;
        r0.x = o[dc][0]*inv0; r0.y = o[dc][1]*inv0;
        r1.x = o[dc][2]*inv1; r1.y = o[dc][3]*inv1;
        *(float2*)(ctx0 + 8*dc + 2*lc) = r0;
        *(float2*)(ctx1 + 8*dc + 2*lc) = r1;
    }
}

// =====================================================================
// launch
// =====================================================================
extern "C" void kernel_launch(void* const* d_in, const int* in_sizes, int n_in,
                              void* d_out, int out_size)
{
    const float* in_q  = (const float*)d_in[0];
    const float* in_k  = (const float*)d_in[1];
    const float* in_v  = (const float*)d_in[2];
    const float* box   = (const float*)d_in[3];
    const float* Wq    = (const float*)d_in[4];
    const float* bq    = (const float*)d_in[5];
    const float* Wk    = (const float*)d_in[6];
    const float* bk    = (const float*)d_in[7];
    const float* Wv    = (const float*)d_in[8];
    const float* bv    = (const float*)d_in[9];
    const float* Wo    = (const float*)d_in[10];
    const float* bo    = (const float*)d_in[11];
    const float* WG    = (const float*)d_in[12];
    const float* bG    = (const float*)d_in[13];
    float* out = (float*)d_out;

    const int ATTN_SMEM = (2*64*QS_STRIDE + 2*64*KS_STRIDE) * (int)sizeof(float); // 71680
    cudaFuncSetAttribute(attn_kernel, cudaFuncAttributeMaxDynamicSharedMemorySize, ATTN_SMEM);

    // geometry bias (software sincosf — verified config, frozen)
    geom_kernel<<<dim3(NTOK, BATCH), 256>>>(box, WG, bG);

    // fused Q/K/V projections (tf32 tensor cores, BK=32)
    qkv_kernel<<<dim3(512/64, 2048/64, 3), 128>>>(in_q, in_k, in_v,
                                                  Wq, Wk, Wv, bq, bk, bv);

    // attention (tf32 tensor cores, latency-hidden staging)
    attn_kernel<<<dim3(BATCH*NH, NTOK/64), 128, ATTN_SMEM>>>();

    // output projection -> d_out (BK=32, plain write)
    oproj_kernel<<<dim3(512/64, 2048/64), 128>>>(Wo, bo, out);
}

// round 15
// speedup vs baseline: 1.7045x; 1.0401x over previous
#include <cuda_runtime.h>
#include <math.h>

#define BATCH   4
#define NTOK    512
#define DMODEL  512
#define NH      8
#define DKH     64

#define QKV_BLOCKS  384    // 3 ops x 16 m-pairs x 8 n-tiles
#define GEOM_BLOCKS 2048   // 512 rows x 4 batches

// ---------------- device scratch (no allocations allowed) ----------------
__device__ float g_Q[BATCH*NH*NTOK*DKH];     // 4 MB
__device__ float g_K[BATCH*NH*NTOK*DKH];     // 4 MB
__device__ float g_V[BATCH*NH*NTOK*DKH];     // 4 MB
__device__ float g_BIAS[BATCH*NH*NTOK*NTOK]; // 32 MB
__device__ float g_CTX[BATCH*NTOK*DMODEL];   // 4 MB

// ---------------- helpers ----------------
__device__ __forceinline__ unsigned f2tf32(float x) {
    unsigned b;
    asm("cvt.rna.tf32.f32 %0, %1;" : "=r"(b) : "f"(x));
    return b;
}
__device__ __forceinline__ float f2tf32f(float x) {
    return __uint_as_float(f2tf32(x));
}

__device__ __forceinline__ void mma_tf32(float& c0, float& c1, float& c2, float& c3,
                                         unsigned a0, unsigned a1, unsigned a2, unsigned a3,
                                         unsigned b0, unsigned b1) {
    asm volatile("mma.sync.aligned.m16n8k8.row.col.f32.tf32.tf32.f32 "
                 "{%0,%1,%2,%3}, {%4,%5,%6,%7}, {%8,%9}, {%0,%1,%2,%3};"
                 : "+f"(c0), "+f"(c1), "+f"(c2), "+f"(c3)
                 : "r"(a0), "r"(a1), "r"(a2), "r"(a3), "r"(b0), "r"(b1));
}

// =====================================================================
// TF32 GEMM 64x64 tile worker, BK=32, 128 threads (tid 0..127).
// smem via pointers so two instances can run in one 256-thread CTA.
// =====================================================================
template<typename WriteFn>
__device__ __forceinline__ void gemm64_half(
    const float* __restrict__ X, const float* __restrict__ W,
    int m0, int n0, int tid, float (*As)[72], float (*Bs)[72],
    WriteFn&& write)
{
    const int lm = tid >> 1;           // row 0..63
    const int lk = (tid & 1) * 16;     // k offset 0 or 16

    const float* Aptr = X + (long)(m0 + lm)*512 + lk;
    const float* Bptr = W + (long)(n0 + lm)*512 + lk;

    float4 xa[4], wa[4];
    #pragma unroll
    for (int u = 0; u < 4; u++) {
        xa[u] = *(const float4*)(Aptr + u*4);
        wa[u] = *(const float4*)(Bptr + u*4);
    }

    const int w    = tid >> 5;
    const int wm   = (w & 1) * 32;
    const int wn2  = (w >> 1) * 32;
    const int lane = tid & 31;
    const int lr   = lane >> 2;
    const int lc   = lane & 3;

    float acc[2][4][4];
    #pragma unroll
    for (int mi = 0; mi < 2; mi++)
        #pragma unroll
        for (int ni = 0; ni < 4; ni++)
            #pragma unroll
            for (int q = 0; q < 4; q++) acc[mi][ni][q] = 0.0f;

    for (int k0 = 0; k0 < 512; k0 += 32) {
        #pragma unroll
        for (int u = 0; u < 4; u++) {
            As[lk+u*4+0][lm]=f2tf32f(xa[u].x); As[lk+u*4+1][lm]=f2tf32f(xa[u].y);
            As[lk+u*4+2][lm]=f2tf32f(xa[u].z); As[lk+u*4+3][lm]=f2tf32f(xa[u].w);
            Bs[lk+u*4+0][lm]=f2tf32f(wa[u].x); Bs[lk+u*4+1][lm]=f2tf32f(wa[u].y);
            Bs[lk+u*4+2][lm]=f2tf32f(wa[u].z); Bs[lk+u*4+3][lm]=f2tf32f(wa[u].w);
        }
        __syncthreads();

        if (k0 + 32 < 512) {
            #pragma unroll
            for (int u = 0; u < 4; u++) {
                xa[u] = *(const float4*)(Aptr + k0 + 32 + u*4);
                wa[u] = *(const float4*)(Bptr + k0 + 32 + u*4);
            }
        }

        #pragma unroll
        for (int ks = 0; ks < 4; ks++) {
            const int kb = ks * 8;
            unsigned afr[2][4];
            #pragma unroll
            for (int mi = 0; mi < 2; mi++) {
                const int mrow = wm + 16*mi;
                afr[mi][0] = __float_as_uint(As[kb + lc    ][mrow + lr    ]);
                afr[mi][1] = __float_as_uint(As[kb + lc    ][mrow + lr + 8]);
                afr[mi][2] = __float_as_uint(As[kb + lc + 4][mrow + lr    ]);
                afr[mi][3] = __float_as_uint(As[kb + lc + 4][mrow + lr + 8]);
            }
            unsigned bfr[4][2];
            #pragma unroll
            for (int ni = 0; ni < 4; ni++) {
                const int ncol = wn2 + 8*ni;
                bfr[ni][0] = __float_as_uint(Bs[kb + lc    ][ncol + lr]);
                bfr[ni][1] = __float_as_uint(Bs[kb + lc + 4][ncol + lr]);
            }
            #pragma unroll
            for (int mi = 0; mi < 2; mi++)
                #pragma unroll
                for (int ni = 0; ni < 4; ni++)
                    mma_tf32(acc[mi][ni][0], acc[mi][ni][1],
                             acc[mi][ni][2], acc[mi][ni][3],
                             afr[mi][0], afr[mi][1], afr[mi][2], afr[mi][3],
                             bfr[ni][0], bfr[ni][1]);
        }
        __syncthreads();
    }

    #pragma unroll
    for (int mi = 0; mi < 2; mi++) {
        #pragma unroll
        for (int ni = 0; ni < 4; ni++) {
            const int row = wm + 16*mi + lr;
            const int col = wn2 + 8*ni + 2*lc;
            write(row,     col, acc[mi][ni][0], acc[mi][ni][1]);
            write(row + 8, col, acc[mi][ni][2], acc[mi][ni][3]);
        }
    }
}

// =====================================================================
// FUSED Kernel 1: geom + qkv in one launch (grid concatenation).
// blocks [0, QKV_BLOCKS): qkv — 256 threads = two 64x64 tile workers.
// blocks [QKV_BLOCKS, +GEOM_BLOCKS): geom — exact verified 256-thread body.
// =====================================================================
__global__ void __launch_bounds__(256) geom_qkv_kernel(
    const float* __restrict__ box, const float* __restrict__ WG,
    const float* __restrict__ bG,
    const float* __restrict__ Xq, const float* __restrict__ Xk,
    const float* __restrict__ Xv,
    const float* __restrict__ Wq, const float* __restrict__ Wk,
    const float* __restrict__ Wv,
    const float* __restrict__ bq, const float* __restrict__ bk,
    const float* __restrict__ bv)
{
    __shared__ float As2[2][32][72];
    __shared__ float Bs2[2][32][72];
    __shared__ float sWGs[32][8];
    __shared__ float sWGc[32][8];
    __shared__ float sbG[8];

    if (blockIdx.x < QKV_BLOCKS) {
        // ------------------- QKV branch -------------------
        const int q   = blockIdx.x;
        const int z   = q >> 7;            // 0..2  (128 blocks per op)
        const int rem = q & 127;
        const int n0  = (rem & 7) * 64;
        const int half = threadIdx.x >> 7; // 0 or 1
        const int m0  = ((rem >> 3) * 2 + half) * 64;
        const int tid = threadIdx.x & 127;

        const float* X    = (z == 0) ? Xq : (z == 1) ? Xk : Xv;
        const float* W    = (z == 0) ? Wq : (z == 1) ? Wk : Wv;
        const float* bias = (z == 0) ? bq : (z == 1) ? bk : bv;
        float*       Y    = (z == 0) ? g_Q : (z == 1) ? g_K : g_V;
        const int h = n0 >> 6;

        gemm64_half(X, W, m0, n0, tid, As2[half], Bs2[half],
            [&](int row, int col, float v0, float v1) {
                int m = m0 + row;
                int b = m >> 9, n = m & 511;
                float2 r;
                r.x = v0 + bias[n0 + col];
                r.y = v1 + bias[n0 + col + 1];
                *(float2*)(Y + (((long)(b*NH + h)*NTOK + n)*DKH) + col) = r;
            });
        return;
    }

    // ------------------- GEOM branch (verified body, frozen) -------------------
    const int g = blockIdx.x - QKV_BLOCKS;
    const int b = g >> 9;
    const int i = g & 511;
    const int tid = threadIdx.x;

    for (int e = tid; e < 512; e += blockDim.x) {
        int h = e >> 6, gg = e & 63;
        float v = WG[e];
        if (gg < 32) sWGs[gg][h] = v;
        else         sWGc[gg - 32][h] = v;
    }
    if (tid < 8) sbG[tid] = bG[tid];

    const float4 bi = *(const float4*)(box + ((long)b*NTOK + i)*4);
    const float cxi = 0.5f*(bi.x + bi.z);
    const float cyi = 0.5f*(bi.y + bi.w);
    const float wi  = bi.z - bi.x + 1.0f;
    const float hi  = bi.w - bi.y + 1.0f;
    const float lwi = logf(wi);
    const float lhi = logf(hi);
    __syncthreads();

    const float dm[8] = {1.0f, 0.4216965034f, 0.1778279410f, 0.0749894209f,
                         0.0316227766f, 0.0133352143f, 0.0056234133f, 0.0023713737f};

    float* outb = g_BIAS + ((long)b*NH*NTOK + i)*NTOK;

    for (int j = tid; j < NTOK; j += blockDim.x) {
        float4 bj = *(const float4*)(box + ((long)b*NTOK + j)*4);
        float cxj = 0.5f*(bj.x + bj.z);
        float cyj = 0.5f*(bj.y + bj.w);
        float wj  = bj.z - bj.x + 1.0f;
        float hj  = bj.w - bj.y + 1.0f;

        float a0 = 100.0f * logf(fmaxf(fabsf(cxi - cxj) / wi, 1e-3f));
        float a1 = 100.0f * logf(fmaxf(fabsf(cyi - cyj) / hi, 1e-3f));
        float a2 = 100.0f * (lwi - logf(wj));
        float a3 = 100.0f * (lhi - logf(hj));
        float a[4] = {a0, a1, a2, a3};

        float acc[8];
        #pragma unroll
        for (int h = 0; h < 8; h++) acc[h] = sbG[h];

        #pragma unroll
        for (int f = 0; f < 4; f++) {
            #pragma unroll
            for (int r = 0; r < 8; r++) {
                float s, c;
                sincosf(a[f] * dm[r], &s, &c);
                const int t = f*8 + r;
                #pragma unroll
                for (int h = 0; h < 8; h++)
                    acc[h] += s * sWGs[t][h] + c * sWGc[t][h];
            }
        }
        #pragma unroll
        for (int h = 0; h < 8; h++) {
            float wg = fmaxf(acc[h], 1e-6f);
            outb[(long)h*NTOK*NTOK + j] = logf(wg);
        }
    }
}

// =====================================================================
// Output projection: 128 threads, single 64x64 tile (BK=32 core).
// =====================================================================
__global__ void __launch_bounds__(128) oproj_kernel(
    const float* __restrict__ W, const float* __restrict__ bias,
    float* __restrict__ Yout)
{
    __shared__ float As[32][72];
    __shared__ float Bs[32][72];

    const int m0 = blockIdx.y * 64;
    const int n0 = blockIdx.x * 64;

    gemm64_half(g_CTX, W, m0, n0, threadIdx.x, As, Bs,
        [&](int row, int col, float v0, float v1) {
            float2 r;
            r.x = v0 + bias[n0 + col];
            r.y = v1 + bias[n0 + col + 1];
            *(float2*)(Yout + (long)(m0 + row)*512 + n0 + col) = r;
        });
}

// =====================================================================
// Kernel 3: flash attention, TF32 mma, latency-hidden staging.
// EXACT verified version (untouched).
// =====================================================================
#define QS_STRIDE 68
#define KS_STRIDE 72

__global__ void __launch_bounds__(128) attn_kernel()
{
    extern __shared__ float sm[];
    float* Qs = sm;                      // [64][68]  m-major (tf32, x0.125)
    float* Ks = Qs + 64*QS_STRIDE;       // [64][72]  k-major
    float* Vs = Ks + 64*KS_STRIDE;       // [64][72]  token-major
    float* Ps = Vs + 64*KS_STRIDE;       // [64][68]  m-major

    const int tid  = threadIdx.x;
    const int lane = tid & 31;
    const int w    = tid >> 5;
    const int wm   = w * 16;
    const int lr   = lane >> 2;
    const int lc   = lane & 3;

    const int bh = blockIdx.x;
    const int q0 = blockIdx.y * 64;

    const float* Qg = g_Q   + (long)bh*NTOK*DKH + (long)q0*DKH;
    const float* Kg = g_K   + (long)bh*NTOK*DKH;
    const float* Vg = g_V   + (long)bh*NTOK*DKH;
    const float* Bg = g_BIAS + (long)bh*NTOK*NTOK + (long)q0*NTOK;

    const int n  = tid >> 1;
    const int kq = (tid & 1) * 32;

    {
        const float* src = Qg + n*64 + kq;
        #pragma unroll
        for (int u = 0; u < 8; u++) {
            float4 v = *(const float4*)(src + u*4);
            Qs[n*QS_STRIDE + kq + u*4 + 0] = f2tf32f(v.x * 0.125f);
            Qs[n*QS_STRIDE + kq + u*4 + 1] = f2tf32f(v.y * 0.125f);
            Qs[n*QS_STRIDE + kq + u*4 + 2] = f2tf32f(v.z * 0.125f);
            Qs[n*QS_STRIDE + kq + u*4 + 3] = f2tf32f(v.w * 0.125f);
        }
    }

    float4 kreg[8];
    {
        const float* srcK = Kg + (long)n*64 + kq;
        #pragma unroll
        for (int u = 0; u < 8; u++) kreg[u] = *(const float4*)(srcK + u*4);
    }

    float m_i[2] = {-1e30f, -1e30f};
    float l_i[2] = {0.0f, 0.0f};
    float o[8][4];
    #pragma unroll
    for (int d = 0; d < 8; d++)
        #pragma unroll
        for (int q = 0; q < 4; q++) o[d][q] = 0.0f;

    for (int t = 0; t < 8; t++) {
        __syncthreads();

        #pragma unroll
        for (int u = 0; u < 8; u++) {
            Ks[(kq+u*4+0)*KS_STRIDE + n] = f2tf32f(kreg[u].x);
            Ks[(kq+u*4+1)*KS_STRIDE + n] = f2tf32f(kreg[u].y);
            Ks[(kq+u*4+2)*KS_STRIDE + n] = f2tf32f(kreg[u].z);
            Ks[(kq+u*4+3)*KS_STRIDE + n] = f2tf32f(kreg[u].w);
        }

        if (t < 7) {
            const float* srcK = Kg + (long)((t+1)*64 + n)*64 + kq;
            #pragma unroll
            for (int u = 0; u < 8; u++) kreg[u] = *(const float4*)(srcK + u*4);
        }

        float4 vreg[8];
        {
            const float* srcV = Vg + (long)(t*64 + n)*64 + kq;
            #pragma unroll
            for (int u = 0; u < 8; u++) vreg[u] = *(const float4*)(srcV + u*4);
        }

        float2 breg0[8], breg1[8];
        {
            const float* brow0 = Bg + (long)(wm+lr  )*512 + t*64;
            const float* brow1 = Bg + (long)(wm+lr+8)*512 + t*64;
            #pragma unroll
            for (int nc = 0; nc < 8; nc++) {
                breg0[nc] = *(const float2*)(brow0 + 8*nc + 2*lc);
                breg1[nc] = *(const float2*)(brow1 + 8*nc + 2*lc);
            }
        }
        __syncthreads();

        float sacc[8][4];
        #pragma unroll
        for (int nc = 0; nc < 8; nc++)
            #pragma unroll
            for (int q = 0; q < 4; q++) sacc[nc][q] = 0.0f;

        #pragma unroll
        for (int ks = 0; ks < 8; ks++) {
            const int kb = ks * 8;
            unsigned a0 = __float_as_uint(Qs[(wm+lr  )*QS_STRIDE + kb + lc    ]);
            unsigned a1 = __float_as_uint(Qs[(wm+lr+8)*QS_STRIDE + kb + lc    ]);
            unsigned a2 = __float_as_uint(Qs[(wm+lr  )*QS_STRIDE + kb + lc + 4]);
            unsigned a3 = __float_as_uint(Qs[(wm+lr+8)*QS_STRIDE + kb + lc + 4]);
            #pragma unroll
            for (int nc = 0; nc < 8; nc++) {
                unsigned b0 = __float_as_uint(Ks[(kb+lc  )*KS_STRIDE + 8*nc + lr]);
                unsigned b1 = __float_as_uint(Ks[(kb+lc+4)*KS_STRIDE + 8*nc + lr]);
                mma_tf32(sacc[nc][0], sacc[nc][1], sacc[nc][2], sacc[nc][3],
                         a0, a1, a2, a3, b0, b1);
            }
        }

        #pragma unroll
        for (int u = 0; u < 8; u++) {
            float4 cv;
            cv.x = f2tf32f(vreg[u].x); cv.y = f2tf32f(vreg[u].y);
            cv.z = f2tf32f(vreg[u].z); cv.w = f2tf32f(vreg[u].w);
            *(float4*)&Vs[n*KS_STRIDE + kq + u*4] = cv;
        }

        #pragma unroll
        for (int nc = 0; nc < 8; nc++) {
            sacc[nc][0] += breg0[nc].x; sacc[nc][1] += breg0[nc].y;
            sacc[nc][2] += breg1[nc].x; sacc[nc][3] += breg1[nc].y;
        }

        #pragma unroll
        for (int i = 0; i < 2; i++) {
            float tm = -1e30f;
            #pragma unroll
            for (int nc = 0; nc < 8; nc++)
                tm = fmaxf(tm, fmaxf(sacc[nc][2*i], sacc[nc][2*i+1]));
            tm = fmaxf(tm, __shfl_xor_sync(0xffffffffu, tm, 1));
            tm = fmaxf(tm, __shfl_xor_sync(0xffffffffu, tm, 2));
            float mnew = fmaxf(m_i[i], tm);
            float scale = __expf(m_i[i] - mnew);
            m_i[i] = mnew;

            float s = 0.0f;
            #pragma unroll
            for (int nc = 0; nc < 8; nc++) {
                float p0 = __expf(sacc[nc][2*i]   - mnew);
                float p1 = __expf(sacc[nc][2*i+1] - mnew);
                sacc[nc][2*i]   = p0;
                sacc[nc][2*i+1] = p1;
                s += p0 + p1;
            }
            s += __shfl_xor_sync(0xffffffffu, s, 1);
            s += __shfl_xor_sync(0xffffffffu, s, 2);
            l_i[i] = l_i[i]*scale + s;

            #pragma unroll
            for (int d = 0; d < 8; d++) {
                o[d][2*i]   *= scale;
                o[d][2*i+1] *= scale;
            }
        }

        #pragma unroll
        for (int nc = 0; nc < 8; nc++) {
            float2 p0, p1;
            p0.x = f2tf32f(sacc[nc][0]); p0.y = f2tf32f(sacc[nc][1]);
            p1.x = f2tf32f(sacc[nc][2]); p1.y = f2tf32f(sacc[nc][3]);
            *(float2*)&Ps[(wm+lr  )*QS_STRIDE + 8*nc + 2*lc] = p0;
            *(float2*)&Ps[(wm+lr+8)*QS_STRIDE + 8*nc + 2*lc] = p1;
        }
        __syncthreads();

        #pragma unroll
        for (int ks = 0; ks < 8; ks++) {
            const int kb = ks * 8;
            unsigned a0 = __float_as_uint(Ps[(wm+lr  )*QS_STRIDE + kb + lc    ]);
            unsigned a1 = __float_as_uint(Ps[(wm+lr+8)*QS_STRIDE + kb + lc    ]);
            unsigned a2 = __float_as_uint(Ps[(wm+lr  )*QS_STRIDE + kb + lc + 4]);
            unsigned a3 = __float_as_uint(Ps[(wm+lr+8)*QS_STRIDE + kb + lc + 4]);
            #pragma unroll
            for (int dc = 0; dc < 8; dc++) {
                unsigned b0 = __float_as_uint(Vs[(kb+lc  )*KS_STRIDE + 8*dc + lr]);
                unsigned b1 = __float_as_uint(Vs[(kb+lc+4)*KS_STRIDE + 8*dc + lr]);
                mma_tf32(o[dc][0], o[dc][1], o[dc][2], o[dc][3],
                         a0, a1, a2, a3, b0, b1);
            }
        }
    }

    const int b = bh >> 3, h = bh & 7;
    const float inv0 = 1.0f / l_i[0];
    const float inv1 = 1.0f / l_i[1];
    float* ctx0 = g_CTX + ((long)(b*NTOK + q0 + wm + lr    ))*512 + h*64;
    float* ctx1 = g_CTX + ((long)(b*NTOK + q0 + wm + lr + 8))*512 + h*64;
    #pragma unroll
    for (int dc = 0; dc < 8; dc++) {
        float2 r0, r1;
        r0.x = o[dc][0]*inv0; r0.y = o[dc][1]*inv0;
        r1.x = o[dc][2]*inv1; r1.y = o[dc][3]*inv1;
        *(float2*)(ctx0 + 8*dc + 2*lc) = r0;
        *(float2*)(ctx1 + 8*dc + 2*lc) = r1;
    }
}

// =====================================================================
// launch
// =====================================================================
extern "C" void kernel_launch(void* const* d_in, const int* in_sizes, int n_in,
                              void* d_out, int out_size)
{
    const float* in_q  = (const float*)d_in[0];
    const float* in_k  = (const float*)d_in[1];
    const float* in_v  = (const float*)d_in[2];
    const float* box   = (const float*)d_in[3];
    const float* Wq    = (const float*)d_in[4];
    const float* bq    = (const float*)d_in[5];
    const float* Wk    = (const float*)d_in[6];
    const float* bk    = (const float*)d_in[7];
    const float* Wv    = (const float*)d_in[8];
    const float* bv    = (const float*)d_in[9];
    const float* Wo    = (const float*)d_in[10];
    const float* bo    = (const float*)d_in[11];
    const float* WG    = (const float*)d_in[12];
    const float* bG    = (const float*)d_in[13];
    float* out = (float*)d_out;

    const int ATTN_SMEM = (2*64*QS_STRIDE + 2*64*KS_STRIDE) * (int)sizeof(float); // 71680
    cudaFuncSetAttribute(attn_kernel, cudaFuncAttributeMaxDynamicSharedMemorySize, ATTN_SMEM);

    // fused geom + qkv (independent work, co-resident on complementary pipes)
    geom_qkv_kernel<<<QKV_BLOCKS + GEOM_BLOCKS, 256>>>(
        box, WG, bG, in_q, in_k, in_v, Wq, Wk, Wv, bq, bk, bv);

    // attention (tf32 tensor cores, latency-hidden staging)
    attn_kernel<<<dim3(BATCH*NH, NTOK/64), 128, ATTN_SMEM>>>();

    // output projection -> d_out (BK=32)
    oproj_kernel<<<dim3(512/64, 2048/64), 128>>>(Wo, bo, out);
}